// round 6
// baseline (speedup 1.0000x reference)
#include <cuda_runtime.h>

#define NLAB 21
#define BB   64
#define TT   512
#define DD   1024
#define ROWS (BB*TT)
#define LOGITS_N  (ROWS*NLAB)
#define LOSS_IDX  LOGITS_N
#define TAGS_BASE (LOGITS_N+1)
#define FULLMASK 0xffffffffu
#define NEG_BIG  (-1e30f)

typedef unsigned long long ull;
__device__ __forceinline__ ull fma2(ull a, ull b, ull c) {
    ull d; asm("fma.rn.f32x2 %0, %1, %2, %3;" : "=l"(d) : "l"(a), "l"(b), "l"(c));
    return d;
}
__device__ __forceinline__ ull pack2(float lo, float hi) {
    ull d; asm("mov.b64 %0, {%1, %2};" : "=l"(d) : "f"(lo), "f"(hi));
    return d;
}
union F4U { float4 f; ull u[2]; };
union F2U { ull u; float2 f; };

// ---------------------------------------------------------------------------
// GEMM: logits = mlm @ W^T + b. 512 blocks x 128 threads.
// Block = 64 rows. X tile (64 rows x 128 k) staged TRANSPOSED in smem via
// coalesced float4 LDG (each 128B line touched once). W tile (21 x 128)
// broadcast from smem. Thread = (row, k-half of tile). No atomics.
// ---------------------------------------------------------------------------
#define XPAD 65
__global__ __launch_bounds__(128)
void gemm_kernel(const float* __restrict__ mlm, const float* __restrict__ W,
                 const float* __restrict__ bias, float* out)
{
    __shared__ float  Xs[128][XPAD];     // 33280 B, transposed x tile
    __shared__ float4 Wq[NLAB * 32];     // 10752 B, W[j][ktile]
    __shared__ float  bias_s[NLAB];

    const int tid  = threadIdx.x;
    const int half = tid >> 6;
    const int rs   = tid & 63;
    const int row  = blockIdx.x * 64 + rs;

    if (blockIdx.x == 0 && tid == 0) out[LOSS_IDX] = 0.0f;
    if (tid < NLAB) bias_s[tid] = bias[tid];

    ull acc[NLAB];
#pragma unroll
    for (int j = 0; j < NLAB; j++) acc[j] = 0ull;

    const float4* mlm4 = (const float4*)mlm;
    const float4* W4   = (const float4*)W;
    const int kbase = half * 64;

    for (int r = 0; r < 8; r++) {
        __syncthreads();
        // stage X tile transposed: rows blk*64..+64, k in [r*128, r*128+128)
#pragma unroll
        for (int i = 0; i < 16; i++) {
            int idx  = tid + i * 128;           // 0..2047
            int rl   = idx >> 5;                // local row 0..63
            int kc   = idx & 31;                // float4 within tile
            float4 v = mlm4[(size_t)(blockIdx.x * 64 + rl) * 256 + r * 32 + kc];
            Xs[kc * 4 + 0][rl] = v.x;
            Xs[kc * 4 + 1][rl] = v.y;
            Xs[kc * 4 + 2][rl] = v.z;
            Xs[kc * 4 + 3][rl] = v.w;
        }
        // stage W tile: 21 x 32 float4
        for (int idx = tid; idx < NLAB * 32; idx += 128) {
            int j = idx >> 5, kc = idx & 31;
            Wq[idx] = W4[j * 256 + r * 32 + kc];
        }
        __syncthreads();

#pragma unroll 4
        for (int kq = 0; kq < 16; kq++) {
            float x0 = Xs[kbase + kq * 4 + 0][rs];
            float x1 = Xs[kbase + kq * 4 + 1][rs];
            float x2 = Xs[kbase + kq * 4 + 2][rs];
            float x3 = Xs[kbase + kq * 4 + 3][rs];
            ull xa = pack2(x0, x1);
            ull xb = pack2(x2, x3);
            const float4* wrow = Wq + (kbase >> 2) + kq;
#pragma unroll
            for (int j = 0; j < NLAB; j++) {
                F4U w; w.f = wrow[j * 32];
                acc[j] = fma2(xa, w.u[0], acc[j]);
                acc[j] = fma2(xb, w.u[1], acc[j]);
            }
        }
    }

    // combine halves through smem (reuse Wq)
    __syncthreads();
    float* sred = (float*)Wq;   // 64 x 22
    if (half == 1) {
#pragma unroll
        for (int j = 0; j < NLAB; j++) {
            F2U a; a.u = acc[j];
            sred[rs * 22 + j] = a.f.x + a.f.y;
        }
    }
    __syncthreads();
    if (half == 0) {
#pragma unroll
        for (int j = 0; j < NLAB; j++) {
            F2U a; a.u = acc[j];
            out[(size_t)row * NLAB + j] =
                a.f.x + a.f.y + sred[rs * 22 + j] + bias_s[j];
        }
    }
}

// ---------------------------------------------------------------------------
// CRF: grid 144 x 128 threads (unchanged from R5 winning structure).
//  blocks 0-63 forward, 64-127 viterbi (w0 chain, w1 staging, w2/w3 lagged
//  backpointer reconstruction), 128-143 joint score.
// ---------------------------------------------------------------------------
__global__ __launch_bounds__(128)
void crf_all(const float* logits, const int* __restrict__ gold,
             const float* __restrict__ trans, const float* __restrict__ startT,
             const float* __restrict__ endT, float* out)
{
    __shared__ float         em[2][64 * NLAB];
    __shared__ float         abuf[2][65][24];
    __shared__ unsigned char bp[TT][24];
    __shared__ unsigned char pathbuf[8][NLAB][64];
    __shared__ float         trans_s[NLAB * NLAB];
    __shared__ unsigned char entry[8][NLAB];
    __shared__ int           sel[8];
    __shared__ int           last_tag_s;

    const int bid  = blockIdx.x;
    const int tid  = threadIdx.x;
    const int warp = tid >> 5;
    const int lane = tid & 31;
    const int j    = (lane < NLAB) ? lane : (NLAB - 1);

    if (bid >= 128) {
        const int b = (bid - 128) * 4 + warp;
        const float* lg = logits + (size_t)b * TT * NLAB;
        const int*   gb = gold + b * TT;
        float jp = 0.0f;
#pragma unroll 4
        for (int t = lane; t < TT; t += 32) {
            int g = gb[t];
            jp += lg[t * NLAB + g];
            if (t == 0)     jp += startT[g];
            if (t < TT - 1) jp += trans[g * NLAB + gb[t + 1]];
            else            jp += endT[g];
        }
#pragma unroll
        for (int w = 16; w; w >>= 1) jp += __shfl_xor_sync(FULLMASK, jp, w);
        if (lane == 0) atomicAdd(&out[LOSS_IDX], -jp);
        return;
    }

    const bool is_fwd = (bid < 64);
    const int  b      = is_fwd ? bid : (bid - 64);
    const float* lg   = logits + (size_t)b * TT * NLAB;

    for (int k = tid; k < NLAB * NLAB; k += 128) trans_s[k] = trans[k];

    float col[NLAB], st_init = 0.0f;
    if (warp == 0) {
        if (is_fwd) {
#pragma unroll
            for (int i = 0; i < NLAB; i++)
                col[i] = (lane < NLAB) ? __expf(trans[i * NLAB + j]) : 0.0f;
            st_init = (lane < NLAB) ? __expf(startT[j]) : 0.0f;
        } else {
#pragma unroll
            for (int i = 0; i < NLAB; i++) col[i] = trans[i * NLAB + j];
            st_init = startT[j];
        }
    }
    if (warp == 1) {
        if (is_fwd) for (int k = lane; k < 64 * NLAB; k += 32) em[0][k] = __expf(lg[k]);
        else        for (int k = lane; k < 64 * NLAB; k += 32) em[0][k] = lg[k];
    }
    __syncthreads();

    float st = 0.0f;
    int  eoff = 0;

    for (int it = 0; it < 9; it++) {
        if (warp == 0 && it < 8) {
            const int c = it, cb = it & 1;
            const float* e = em[cb];
            if (lane < NLAB) abuf[cb][0][lane] = st;
#pragma unroll 1
            for (int s = 0; s < 64; s++) {
                __syncwarp();
                if (c == 0 && s == 0) {
                    st = is_fwd ? (st_init * e[j]) : (st_init + e[j]);
                } else {
                    const float* row = abuf[cb][s];
                    float4 A0 = *(const float4*)(row);
                    float4 A1 = *(const float4*)(row + 4);
                    float4 A2 = *(const float4*)(row + 8);
                    float4 A3 = *(const float4*)(row + 12);
                    float4 A4 = *(const float4*)(row + 16);
                    float  a20 = row[20];
                    float  ev  = e[s * NLAB + j];
                    if (is_fwd) {
                        float u0 = A0.x*col[0]  + A1.w*col[7]  + A3.z*col[14];
                        float u1 = A0.y*col[1]  + A2.x*col[8]  + A3.w*col[15];
                        float u2 = A0.z*col[2]  + A2.y*col[9]  + A4.x*col[16];
                        float u3 = A0.w*col[3]  + A2.z*col[10] + A4.y*col[17];
                        float u4 = A1.x*col[4]  + A2.w*col[11] + A4.z*col[18];
                        float u5 = A1.y*col[5]  + A3.x*col[12] + A4.w*col[19];
                        float u6 = A1.z*col[6]  + A3.y*col[13] + a20*col[20];
                        st = (((u0 + u1) + (u2 + u3)) + ((u4 + u5) + u6)) * ev;
                        if ((s & 7) == 7) {
                            unsigned eb = __float_as_uint(A0.x) >> 23;
                            eoff += (int)eb - 127;
                            st *= __uint_as_float((254u - eb) << 23);
                        }
                    } else {
                        float v0  = A0.x + col[0],  v1  = A0.y + col[1];
                        float v2  = A0.z + col[2],  v3  = A0.w + col[3];
                        float v4  = A1.x + col[4],  v5  = A1.y + col[5];
                        float v6  = A1.z + col[6],  v7  = A1.w + col[7];
                        float v8  = A2.x + col[8],  v9  = A2.y + col[9];
                        float v10 = A2.z + col[10], v11 = A2.w + col[11];
                        float v12 = A3.x + col[12], v13 = A3.y + col[13];
                        float v14 = A3.z + col[14], v15 = A3.w + col[15];
                        float v16 = A4.x + col[16], v17 = A4.y + col[17];
                        float v18 = A4.z + col[18], v19 = A4.w + col[19];
                        float v20 = a20 + col[20];
                        float m0 = fmaxf(v0, v1),   m1 = fmaxf(v2, v3);
                        float m2 = fmaxf(v4, v5),   m3 = fmaxf(v6, v7);
                        float m4 = fmaxf(v8, v9),   m5 = fmaxf(v10, v11);
                        float m6 = fmaxf(v12, v13), m7 = fmaxf(v14, v15);
                        float m8 = fmaxf(v16, v17), m9 = fmaxf(v18, v19);
                        float n0 = fmaxf(m0, m1), n1 = fmaxf(m2, m3);
                        float n2 = fmaxf(m4, m5), n3 = fmaxf(m6, m7);
                        float n4 = fmaxf(m8, m9);
                        st = fmaxf(fmaxf(fmaxf(n0, n1), fmaxf(n2, n3)),
                                   fmaxf(n4, v20)) + ev;
                    }
                }
                if (lane < NLAB) abuf[cb][s + 1][lane] = st;
            }
        }
        if (warp == 1 && it < 7) {
            const float* src = lg + (it + 1) * 64 * NLAB;
            float* dst = em[(it + 1) & 1];
            if (is_fwd) for (int k = lane; k < 64 * NLAB; k += 32) dst[k] = __expf(src[k]);
            else        for (int k = lane; k < 64 * NLAB; k += 32) dst[k] = src[k];
        }
        if (!is_fwd && warp >= 2 && it >= 1) {
            const int c = it - 1, cb = c & 1;
            const int w = tid - 64;
            for (int task = w; task < 64 * NLAB; task += 64) {
                int s  = task / NLAB;
                int jo = task - s * NLAB;
                if (c == 0 && s == 0) continue;
                const float* row = abuf[cb][s];
                const float* tc  = trans_s + jo;
                float v[21];
#pragma unroll
                for (int i = 0; i < 21; i++) v[i] = row[i] + tc[i * NLAB];
                float m0 = fmaxf(v[0], v[1]),   m1 = fmaxf(v[2], v[3]);
                float m2 = fmaxf(v[4], v[5]),   m3 = fmaxf(v[6], v[7]);
                float m4 = fmaxf(v[8], v[9]),   m5 = fmaxf(v[10], v[11]);
                float m6 = fmaxf(v[12], v[13]), m7 = fmaxf(v[14], v[15]);
                float m8 = fmaxf(v[16], v[17]), m9 = fmaxf(v[18], v[19]);
                float best = fmaxf(fmaxf(fmaxf(fmaxf(m0, m1), fmaxf(m2, m3)),
                                         fmaxf(fmaxf(m4, m5), fmaxf(m6, m7))),
                                   fmaxf(fmaxf(m8, m9), v[20]));
                int idx = 20;
#pragma unroll
                for (int i = 19; i >= 0; i--) idx = (v[i] == best) ? i : idx;
                bp[c * 64 + s][jo] = (unsigned char)idx;
            }
        }
        __syncthreads();
    }

    if (is_fwd) {
        if (warp == 0) {
            float val = (lane < NLAB) ? st * __expf(endT[j]) : 0.0f;
#pragma unroll
            for (int w = 16; w; w >>= 1) val += __shfl_xor_sync(FULLMASK, val, w);
            if (lane == 0)
                atomicAdd(&out[LOSS_IDX],
                          (float)eoff * 0.69314718055994531f + __logf(val));
        }
        return;
    }

    if (warp == 0) {
        float v = (lane < NLAB) ? (st + endT[j]) : NEG_BIG;
        float m = v;
#pragma unroll
        for (int w = 16; w; w >>= 1) m = fmaxf(m, __shfl_xor_sync(FULLMASK, m, w));
        unsigned bal = __ballot_sync(FULLMASK, v == m);
        if (lane == 0) last_tag_s = __ffs(bal) - 1;
    }
    __syncthreads();

    for (int task = tid; task < 8 * NLAB; task += 128) {
        int c = task / NLAB, jj = task - (task / NLAB) * NLAB;
        int x = jj;
        pathbuf[c][jj][63] = (unsigned char)x;
#pragma unroll 1
        for (int s = 63; s >= 1; s--) {
            x = bp[c * 64 + s][x];
            pathbuf[c][jj][s - 1] = (unsigned char)x;
        }
        entry[c][jj] = (c > 0) ? bp[c * 64][x] : (unsigned char)0;
    }
    __syncthreads();
    if (tid == 0) {
        int x = last_tag_s;
#pragma unroll
        for (int c = 7; c >= 0; c--) { sel[c] = x; x = entry[c][x]; }
    }
    __syncthreads();
    for (int t = tid; t < TT; t += 128) {
        int c = t >> 6;
        out[TAGS_BASE + (size_t)b * TT + t] = (float)pathbuf[c][sel[c]][t & 63];
    }
}

extern "C" void kernel_launch(void* const* d_in, const int* in_sizes, int n_in,
                              void* d_out, int out_size)
{
    const float* mlm    = (const float*)d_in[0];
    const int*   gold   = (const int*)  d_in[2];
    const float* W      = (const float*)d_in[3];
    const float* bias   = (const float*)d_in[4];
    const float* trans  = (const float*)d_in[5];
    const float* startT = (const float*)d_in[6];
    const float* endT   = (const float*)d_in[7];
    float* out = (float*)d_out;

    gemm_kernel<<<512, 128>>>(mlm, W, bias, out);
    crf_all<<<144, 128>>>(out, gold, trans, startT, endT, out);
}

// round 7
// speedup vs baseline: 1.0889x; 1.0889x over previous
#include <cuda_runtime.h>

#define NLAB 21
#define BB   64
#define TT   512
#define DD   1024
#define ROWS (BB*TT)
#define LOGITS_N  (ROWS*NLAB)
#define LOSS_IDX  LOGITS_N
#define TAGS_BASE (LOGITS_N+1)
#define FULLMASK 0xffffffffu
#define NEG_BIG  (-1e30f)

typedef unsigned long long ull;
__device__ __forceinline__ ull fma2(ull a, ull b, ull c) {
    ull d; asm("fma.rn.f32x2 %0, %1, %2, %3;" : "=l"(d) : "l"(a), "l"(b), "l"(c));
    return d;
}
union F4U { float4 f; ull u[2]; };
union F2U { ull u; float2 f; };

__device__ float g_alpha[BB * TT * 24];   // viterbi alpha rows (padded to 24)
__device__ int   g_lasttag[BB];

// ---------------------------------------------------------------------------
// k0: zero the loss accumulator
// ---------------------------------------------------------------------------
__global__ void k0_init(float* out) { if (threadIdx.x == 0) out[LOSS_IDX] = 0.0f; }

// ---------------------------------------------------------------------------
// k1 GEMM: logits = mlm @ W^T + b.  128 blocks x 128 threads.
// Block = 256 rows, thread = rows (tid, tid+128), k-tile = 32 floats (8 f4).
// X staged transposed at float4 granularity: Xs4T[kq][row], pitch 259 f4.
// Register prefetch of next tile hides LDG latency; single smem buffer.
// ---------------------------------------------------------------------------
#define PITCH4 259
__global__ __launch_bounds__(128)
void gemm_kernel(const float* __restrict__ mlm, const float* __restrict__ W,
                 const float* __restrict__ bias, float* out)
{
    __shared__ float4 Xs4[8 * PITCH4];   // 33152 B
    __shared__ float4 Wq4[NLAB * 8];     // 2688 B
    __shared__ float  bias_s[NLAB];

    const int tid = threadIdx.x;
    const int R0  = blockIdx.x * 256;
    if (tid < NLAB) bias_s[tid] = bias[tid];

    const float4* mlm4 = (const float4*)mlm;
    const float4* W4   = (const float4*)W;

    // staging geometry: kc fixed per thread, rows rl = (tid>>3) + 16*i
    const int kc  = tid & 7;
    const int rlb = tid >> 3;

    ull acc0[NLAB], acc1[NLAB];
#pragma unroll
    for (int j = 0; j < NLAB; j++) { acc0[j] = 0ull; acc1[j] = 0ull; }

    float4 nv[16], nw0, nw1;
    // preload tile 0
#pragma unroll
    for (int i = 0; i < 16; i++)
        nv[i] = mlm4[(size_t)(R0 + rlb + 16 * i) * 256 + kc];
    {
        int i2 = tid;            // 0..127  -> always < 168
        nw0 = W4[(i2 >> 3) * 256 + (i2 & 7)];
        int i3 = tid + 128;      // 128..255 -> valid if < 168
        nw1 = (i3 < NLAB * 8) ? W4[(i3 >> 3) * 256 + (i3 & 7)] : make_float4(0, 0, 0, 0);
    }
#pragma unroll
    for (int i = 0; i < 16; i++) Xs4[kc * PITCH4 + rlb + 16 * i] = nv[i];
    Wq4[tid % (NLAB * 8)] = (tid < NLAB * 8) ? nw0 : Wq4[tid % (NLAB * 8)];
    if (tid < NLAB * 8) Wq4[tid] = nw0;
    if (tid + 128 < NLAB * 8) Wq4[tid + 128] = nw1;
    __syncthreads();

#pragma unroll 1
    for (int tile = 0; tile < 32; tile++) {
        // prefetch next tile into registers
        if (tile < 31) {
            const int tb = (tile + 1) * 8;
#pragma unroll
            for (int i = 0; i < 16; i++)
                nv[i] = mlm4[(size_t)(R0 + rlb + 16 * i) * 256 + tb + kc];
            nw0 = W4[(tid >> 3) * 256 + tb + (tid & 7)];
            if (tid + 128 < NLAB * 8)
                nw1 = W4[((tid + 128) >> 3) * 256 + tb + ((tid + 128) & 7)];
        }
        // compute current tile
#pragma unroll 2
        for (int kq = 0; kq < 8; kq++) {
            F4U x0, x1;
            x0.f = Xs4[kq * PITCH4 + tid];
            x1.f = Xs4[kq * PITCH4 + tid + 128];
#pragma unroll
            for (int j = 0; j < NLAB; j++) {
                F4U w; w.f = Wq4[j * 8 + kq];
                acc0[j] = fma2(x0.u[0], w.u[0], acc0[j]);
                acc0[j] = fma2(x0.u[1], w.u[1], acc0[j]);
                acc1[j] = fma2(x1.u[0], w.u[0], acc1[j]);
                acc1[j] = fma2(x1.u[1], w.u[1], acc1[j]);
            }
        }
        __syncthreads();
        if (tile < 31) {
#pragma unroll
            for (int i = 0; i < 16; i++) Xs4[kc * PITCH4 + rlb + 16 * i] = nv[i];
            if (tid < NLAB * 8) Wq4[tid] = nw0;
            if (tid + 128 < NLAB * 8) Wq4[tid + 128] = nw1;
        }
        __syncthreads();
    }

#pragma unroll
    for (int j = 0; j < NLAB; j++) {
        F2U a;
        a.u = acc0[j];
        out[(size_t)(R0 + tid) * NLAB + j] = a.f.x + a.f.y + bias_s[j];
        a.u = acc1[j];
        out[(size_t)(R0 + tid + 128) * NLAB + j] = a.f.x + a.f.y + bias_s[j];
    }
}

// ---------------------------------------------------------------------------
// k2 chains: grid 160 x 64.
//  blocks 0-63 forward (logZ), 64-127 viterbi max-chain (alphas -> gmem),
//  128-159 joint score (2 batches per block).
// ---------------------------------------------------------------------------
__global__ __launch_bounds__(64)
void crf_chain(const float* logits, const int* __restrict__ gold,
               const float* __restrict__ trans, const float* __restrict__ startT,
               const float* __restrict__ endT, float* out)
{
    __shared__ float em[2][64 * NLAB];    // 10752
    __shared__ float abuf[2][65][24];     // 12480

    const int bid  = blockIdx.x;
    const int tid  = threadIdx.x;
    const int warp = tid >> 5;
    const int lane = tid & 31;
    const int j    = (lane < NLAB) ? lane : (NLAB - 1);

    if (bid >= 128) {   // joint score
        const int b = (bid - 128) * 2 + warp;
        const float* lg = logits + (size_t)b * TT * NLAB;
        const int*   gb = gold + b * TT;
        float jp = 0.0f;
#pragma unroll 4
        for (int t = lane; t < TT; t += 32) {
            int g = gb[t];
            jp += lg[t * NLAB + g];
            if (t == 0)     jp += startT[g];
            if (t < TT - 1) jp += trans[g * NLAB + gb[t + 1]];
            else            jp += endT[g];
        }
#pragma unroll
        for (int w = 16; w; w >>= 1) jp += __shfl_xor_sync(FULLMASK, jp, w);
        if (lane == 0) atomicAdd(&out[LOSS_IDX], -jp);
        return;
    }

    const bool is_fwd = (bid < 64);
    const int  b      = is_fwd ? bid : (bid - 64);
    const float* lg   = logits + (size_t)b * TT * NLAB;

    float col[NLAB], st_init = 0.0f;
    if (warp == 0) {
        if (is_fwd) {
#pragma unroll
            for (int i = 0; i < NLAB; i++)
                col[i] = (lane < NLAB) ? __expf(trans[i * NLAB + j]) : 0.0f;
            st_init = (lane < NLAB) ? __expf(startT[j]) : 0.0f;
        } else {
#pragma unroll
            for (int i = 0; i < NLAB; i++) col[i] = trans[i * NLAB + j];
            st_init = startT[j];
        }
    }
    if (warp == 1) {
        if (is_fwd) for (int k = lane; k < 64 * NLAB; k += 32) em[0][k] = __expf(lg[k]);
        else        for (int k = lane; k < 64 * NLAB; k += 32) em[0][k] = lg[k];
    }
    __syncthreads();

    float st = 0.0f;
    int  eoff = 0;

    for (int it = 0; it < 9; it++) {
        if (warp == 0 && it < 8) {
            const int c = it, cb = it & 1;
            const float* e = em[cb];
            if (lane < NLAB) abuf[cb][0][lane] = st;
#pragma unroll 1
            for (int s = 0; s < 64; s++) {
                __syncwarp();
                if (c == 0 && s == 0) {
                    st = is_fwd ? (st_init * e[j]) : (st_init + e[j]);
                } else {
                    const float* row = abuf[cb][s];
                    float4 A0 = *(const float4*)(row);
                    float4 A1 = *(const float4*)(row + 4);
                    float4 A2 = *(const float4*)(row + 8);
                    float4 A3 = *(const float4*)(row + 12);
                    float4 A4 = *(const float4*)(row + 16);
                    float  a20 = row[20];
                    float  ev  = e[s * NLAB + j];
                    if (is_fwd) {
                        float u0 = A0.x*col[0]  + A1.w*col[7]  + A3.z*col[14];
                        float u1 = A0.y*col[1]  + A2.x*col[8]  + A3.w*col[15];
                        float u2 = A0.z*col[2]  + A2.y*col[9]  + A4.x*col[16];
                        float u3 = A0.w*col[3]  + A2.z*col[10] + A4.y*col[17];
                        float u4 = A1.x*col[4]  + A2.w*col[11] + A4.z*col[18];
                        float u5 = A1.y*col[5]  + A3.x*col[12] + A4.w*col[19];
                        float u6 = A1.z*col[6]  + A3.y*col[13] + a20*col[20];
                        st = (((u0 + u1) + (u2 + u3)) + ((u4 + u5) + u6)) * ev;
                        if ((s & 7) == 7) {
                            unsigned eb = __float_as_uint(A0.x) >> 23;
                            eoff += (int)eb - 127;
                            st *= __uint_as_float((254u - eb) << 23);
                        }
                    } else {
                        float v0  = A0.x + col[0],  v1  = A0.y + col[1];
                        float v2  = A0.z + col[2],  v3  = A0.w + col[3];
                        float v4  = A1.x + col[4],  v5  = A1.y + col[5];
                        float v6  = A1.z + col[6],  v7  = A1.w + col[7];
                        float v8  = A2.x + col[8],  v9  = A2.y + col[9];
                        float v10 = A2.z + col[10], v11 = A2.w + col[11];
                        float v12 = A3.x + col[12], v13 = A3.y + col[13];
                        float v14 = A3.z + col[14], v15 = A3.w + col[15];
                        float v16 = A4.x + col[16], v17 = A4.y + col[17];
                        float v18 = A4.z + col[18], v19 = A4.w + col[19];
                        float v20 = a20 + col[20];
                        float m0 = fmaxf(v0, v1),   m1 = fmaxf(v2, v3);
                        float m2 = fmaxf(v4, v5),   m3 = fmaxf(v6, v7);
                        float m4 = fmaxf(v8, v9),   m5 = fmaxf(v10, v11);
                        float m6 = fmaxf(v12, v13), m7 = fmaxf(v14, v15);
                        float m8 = fmaxf(v16, v17), m9 = fmaxf(v18, v19);
                        float n0 = fmaxf(m0, m1), n1 = fmaxf(m2, m3);
                        float n2 = fmaxf(m4, m5), n3 = fmaxf(m6, m7);
                        float n4 = fmaxf(m8, m9);
                        st = fmaxf(fmaxf(fmaxf(n0, n1), fmaxf(n2, n3)),
                                   fmaxf(n4, v20)) + ev;
                    }
                }
                if (lane < NLAB) abuf[cb][s + 1][lane] = st;
            }
        }
        if (warp == 1) {
            if (it < 7) {   // stage chunk it+1
                const float* src = lg + (it + 1) * 64 * NLAB;
                float* dst = em[(it + 1) & 1];
                if (is_fwd) for (int k = lane; k < 64 * NLAB; k += 32) dst[k] = __expf(src[k]);
                else        for (int k = lane; k < 64 * NLAB; k += 32) dst[k] = src[k];
            }
            if (!is_fwd && it >= 1) {   // export alphas of chunk it-1
                const int c = it - 1;
                const float* src = &abuf[c & 1][1][0];
                float* dst = g_alpha + ((size_t)b * TT + c * 64) * 24;
                for (int k = lane; k < 64 * 24; k += 32) dst[k] = src[k];
            }
        }
        __syncthreads();
    }

    if (is_fwd) {
        if (warp == 0) {
            float val = (lane < NLAB) ? st * __expf(endT[j]) : 0.0f;
#pragma unroll
            for (int w = 16; w; w >>= 1) val += __shfl_xor_sync(FULLMASK, val, w);
            if (lane == 0)
                atomicAdd(&out[LOSS_IDX],
                          (float)eoff * 0.69314718055994531f + __logf(val));
        }
    } else {
        if (warp == 0) {
            float v = (lane < NLAB) ? (st + endT[j]) : NEG_BIG;
            float m = v;
#pragma unroll
            for (int w = 16; w; w >>= 1) m = fmaxf(m, __shfl_xor_sync(FULLMASK, m, w));
            unsigned bal = __ballot_sync(FULLMASK, v == m);
            if (lane == 0) g_lasttag[b] = __ffs(bal) - 1;
        }
    }
}

// ---------------------------------------------------------------------------
// k3 finalize: 64 blocks x 128. Rebuild backpointers from exported alphas,
// parallel chunked backtrace, write tags.
// ---------------------------------------------------------------------------
__global__ __launch_bounds__(128)
void crf_fin(const float* __restrict__ trans, float* out)
{
    __shared__ float         alpha_s[128][24];      // 12288
    __shared__ unsigned char bp[TT][24];            // 12288
    __shared__ unsigned char pathbuf[8][NLAB][64];  // 10752
    __shared__ float         trans_s[NLAB * NLAB];  // 1764
    __shared__ unsigned char entry[8][NLAB];
    __shared__ int           sel[8];

    const int b   = blockIdx.x;
    const int tid = threadIdx.x;

    for (int k = tid; k < NLAB * NLAB; k += 128) trans_s[k] = trans[k];

    for (int cc = 0; cc < 4; cc++) {
        __syncthreads();
        const float* src = g_alpha + ((size_t)b * TT + cc * 128) * 24;
        for (int k = tid; k < 128 * 24; k += 128) ((float*)alpha_s)[k] = src[k];
        __syncthreads();
        for (int task = tid; task < 128 * NLAB; task += 128) {
            int tl = task / NLAB;
            int jo = task - tl * NLAB;
            int t  = cc * 128 + 1 + tl;
            if (t >= TT + 1) continue;
            if (t > TT - 1) continue;
            const float* row = alpha_s[tl];
            const float* tc  = trans_s + jo;
            float v[21];
#pragma unroll
            for (int i = 0; i < 21; i++) v[i] = row[i] + tc[i * NLAB];
            float m0 = fmaxf(v[0], v[1]),   m1 = fmaxf(v[2], v[3]);
            float m2 = fmaxf(v[4], v[5]),   m3 = fmaxf(v[6], v[7]);
            float m4 = fmaxf(v[8], v[9]),   m5 = fmaxf(v[10], v[11]);
            float m6 = fmaxf(v[12], v[13]), m7 = fmaxf(v[14], v[15]);
            float m8 = fmaxf(v[16], v[17]), m9 = fmaxf(v[18], v[19]);
            float best = fmaxf(fmaxf(fmaxf(fmaxf(m0, m1), fmaxf(m2, m3)),
                                     fmaxf(fmaxf(m4, m5), fmaxf(m6, m7))),
                               fmaxf(fmaxf(m8, m9), v[20]));
            int idx = 20;
#pragma unroll
            for (int i = 19; i >= 0; i--) idx = (v[i] == best) ? i : idx;
            bp[t][jo] = (unsigned char)idx;
        }
    }
    __syncthreads();

    for (int task = tid; task < 8 * NLAB; task += 128) {
        int c = task / NLAB, jj = task - (task / NLAB) * NLAB;
        int x = jj;
        pathbuf[c][jj][63] = (unsigned char)x;
#pragma unroll 1
        for (int s = 63; s >= 1; s--) {
            x = bp[c * 64 + s][x];
            pathbuf[c][jj][s - 1] = (unsigned char)x;
        }
        entry[c][jj] = (c > 0) ? bp[c * 64][x] : (unsigned char)0;
    }
    __syncthreads();
    if (tid == 0) {
        int x = g_lasttag[b];
#pragma unroll
        for (int c = 7; c >= 0; c--) { sel[c] = x; x = entry[c][x]; }
    }
    __syncthreads();
    for (int t = tid; t < TT; t += 128) {
        int c = t >> 6;
        out[TAGS_BASE + (size_t)b * TT + t] = (float)pathbuf[c][sel[c]][t & 63];
    }
}

extern "C" void kernel_launch(void* const* d_in, const int* in_sizes, int n_in,
                              void* d_out, int out_size)
{
    const float* mlm    = (const float*)d_in[0];
    const int*   gold   = (const int*)  d_in[2];
    const float* W      = (const float*)d_in[3];
    const float* bias   = (const float*)d_in[4];
    const float* trans  = (const float*)d_in[5];
    const float* startT = (const float*)d_in[6];
    const float* endT   = (const float*)d_in[7];
    float* out = (float*)d_out;

    k0_init<<<1, 32>>>(out);
    gemm_kernel<<<128, 128>>>(mlm, W, bias, out);
    crf_chain<<<160, 64>>>(out, gold, trans, startT, endT, out);
    crf_fin<<<64, 128>>>(trans, out);
}

// round 8
// speedup vs baseline: 1.1337x; 1.0412x over previous
#include <cuda_runtime.h>

#define NLAB 21
#define BB   64
#define TT   512
#define DD   1024
#define ROWS (BB*TT)
#define LOGITS_N  (ROWS*NLAB)
#define LOSS_IDX  LOGITS_N
#define TAGS_BASE (LOGITS_N+1)
#define FULLMASK 0xffffffffu
#define NEG_BIG  (-1e30f)

typedef unsigned long long ull;
__device__ __forceinline__ ull fma2(ull a, ull b, ull c) {
    ull d; asm("fma.rn.f32x2 %0, %1, %2, %3;" : "=l"(d) : "l"(a), "l"(b), "l"(c));
    return d;
}
union F4U { float4 f; ull u[2]; };
union F2U { ull u; float2 f; };

__device__ float g_alpha[BB * TT * 24];   // alpha rows, padded to 24 floats
__device__ int   g_lasttag[BB];

// ---------------------------------------------------------------------------
// k1 GEMM: logits = mlm @ W^T + b.  128 blocks x 128 threads. (R7 structure)
// ---------------------------------------------------------------------------
#define PITCH4 259
__global__ __launch_bounds__(128)
void gemm_kernel(const float* __restrict__ mlm, const float* __restrict__ W,
                 const float* __restrict__ bias, float* out)
{
    __shared__ float4 Xs4[8 * PITCH4];
    __shared__ float4 Wq4[NLAB * 8];
    __shared__ float  bias_s[NLAB];

    const int tid = threadIdx.x;
    const int R0  = blockIdx.x * 256;
    if (blockIdx.x == 0 && tid == 0) out[LOSS_IDX] = 0.0f;
    if (tid < NLAB) bias_s[tid] = bias[tid];

    const float4* mlm4 = (const float4*)mlm;
    const float4* W4   = (const float4*)W;
    const int kc  = tid & 7;
    const int rlb = tid >> 3;

    ull acc0[NLAB], acc1[NLAB];
#pragma unroll
    for (int j = 0; j < NLAB; j++) { acc0[j] = 0ull; acc1[j] = 0ull; }

    float4 nv[16], nw0, nw1;
#pragma unroll
    for (int i = 0; i < 16; i++)
        nv[i] = mlm4[(size_t)(R0 + rlb + 16 * i) * 256 + kc];
    nw0 = W4[(tid >> 3) * 256 + (tid & 7)];
    nw1 = (tid + 128 < NLAB * 8)
        ? W4[((tid + 128) >> 3) * 256 + ((tid + 128) & 7)] : make_float4(0, 0, 0, 0);
#pragma unroll
    for (int i = 0; i < 16; i++) Xs4[kc * PITCH4 + rlb + 16 * i] = nv[i];
    if (tid < NLAB * 8) Wq4[tid] = nw0;
    if (tid + 128 < NLAB * 8) Wq4[tid + 128] = nw1;
    __syncthreads();

#pragma unroll 1
    for (int tile = 0; tile < 32; tile++) {
        if (tile < 31) {
            const int tb = (tile + 1) * 8;
#pragma unroll
            for (int i = 0; i < 16; i++)
                nv[i] = mlm4[(size_t)(R0 + rlb + 16 * i) * 256 + tb + kc];
            nw0 = W4[(tid >> 3) * 256 + tb + (tid & 7)];
            if (tid + 128 < NLAB * 8)
                nw1 = W4[((tid + 128) >> 3) * 256 + tb + ((tid + 128) & 7)];
        }
#pragma unroll 2
        for (int kq = 0; kq < 8; kq++) {
            F4U x0, x1;
            x0.f = Xs4[kq * PITCH4 + tid];
            x1.f = Xs4[kq * PITCH4 + tid + 128];
#pragma unroll
            for (int j = 0; j < NLAB; j++) {
                F4U w; w.f = Wq4[j * 8 + kq];
                acc0[j] = fma2(x0.u[0], w.u[0], acc0[j]);
                acc0[j] = fma2(x0.u[1], w.u[1], acc0[j]);
                acc1[j] = fma2(x1.u[0], w.u[0], acc1[j]);
                acc1[j] = fma2(x1.u[1], w.u[1], acc1[j]);
            }
        }
        __syncthreads();
        if (tile < 31) {
#pragma unroll
            for (int i = 0; i < 16; i++) Xs4[kc * PITCH4 + rlb + 16 * i] = nv[i];
            if (tid < NLAB * 8) Wq4[tid] = nw0;
            if (tid + 128 < NLAB * 8) Wq4[tid + 128] = nw1;
        }
        __syncthreads();
    }
#pragma unroll
    for (int j = 0; j < NLAB; j++) {
        F2U a;
        a.u = acc0[j];
        out[(size_t)(R0 + tid) * NLAB + j] = a.f.x + a.f.y + bias_s[j];
        a.u = acc1[j];
        out[(size_t)(R0 + tid + 128) * NLAB + j] = a.f.x + a.f.y + bias_s[j];
    }
}

// ---------------------------------------------------------------------------
// k2 chains: grid 160 x 64. 0-63 fwd, 64-127 viterbi (alphas->gmem), 128-159
// joint score. (R7 structure; float4 alpha export)
// ---------------------------------------------------------------------------
__global__ __launch_bounds__(64)
void crf_chain(const float* logits, const int* __restrict__ gold,
               const float* __restrict__ trans, const float* __restrict__ startT,
               const float* __restrict__ endT, float* out)
{
    __shared__ float em[2][64 * NLAB];
    __shared__ float abuf[2][65][24];

    const int bid  = blockIdx.x;
    const int tid  = threadIdx.x;
    const int warp = tid >> 5;
    const int lane = tid & 31;
    const int j    = (lane < NLAB) ? lane : (NLAB - 1);

    if (bid >= 128) {
        const int b = (bid - 128) * 2 + warp;
        const float* lg = logits + (size_t)b * TT * NLAB;
        const int*   gb = gold + b * TT;
        float jp = 0.0f;
#pragma unroll 4
        for (int t = lane; t < TT; t += 32) {
            int g = gb[t];
            jp += lg[t * NLAB + g];
            if (t == 0)     jp += startT[g];
            if (t < TT - 1) jp += trans[g * NLAB + gb[t + 1]];
            else            jp += endT[g];
        }
#pragma unroll
        for (int w = 16; w; w >>= 1) jp += __shfl_xor_sync(FULLMASK, jp, w);
        if (lane == 0) atomicAdd(&out[LOSS_IDX], -jp);
        return;
    }

    const bool is_fwd = (bid < 64);
    const int  b      = is_fwd ? bid : (bid - 64);
    const float* lg   = logits + (size_t)b * TT * NLAB;

    float col[NLAB], st_init = 0.0f;
    if (warp == 0) {
        if (is_fwd) {
#pragma unroll
            for (int i = 0; i < NLAB; i++)
                col[i] = (lane < NLAB) ? __expf(trans[i * NLAB + j]) : 0.0f;
            st_init = (lane < NLAB) ? __expf(startT[j]) : 0.0f;
        } else {
#pragma unroll
            for (int i = 0; i < NLAB; i++) col[i] = trans[i * NLAB + j];
            st_init = startT[j];
        }
    }
    if (warp == 1) {
        if (is_fwd) for (int k = lane; k < 64 * NLAB; k += 32) em[0][k] = __expf(lg[k]);
        else        for (int k = lane; k < 64 * NLAB; k += 32) em[0][k] = lg[k];
    }
    __syncthreads();

    float st = 0.0f;
    int  eoff = 0;

    for (int it = 0; it < 9; it++) {
        if (warp == 0 && it < 8) {
            const int c = it, cb = it & 1;
            const float* e = em[cb];
            if (lane < NLAB) abuf[cb][0][lane] = st;
#pragma unroll 1
            for (int s = 0; s < 64; s++) {
                __syncwarp();
                if (c == 0 && s == 0) {
                    st = is_fwd ? (st_init * e[j]) : (st_init + e[j]);
                } else {
                    const float* row = abuf[cb][s];
                    float4 A0 = *(const float4*)(row);
                    float4 A1 = *(const float4*)(row + 4);
                    float4 A2 = *(const float4*)(row + 8);
                    float4 A3 = *(const float4*)(row + 12);
                    float4 A4 = *(const float4*)(row + 16);
                    float  a20 = row[20];
                    float  ev  = e[s * NLAB + j];
                    if (is_fwd) {
                        float u0 = A0.x*col[0]  + A1.w*col[7]  + A3.z*col[14];
                        float u1 = A0.y*col[1]  + A2.x*col[8]  + A3.w*col[15];
                        float u2 = A0.z*col[2]  + A2.y*col[9]  + A4.x*col[16];
                        float u3 = A0.w*col[3]  + A2.z*col[10] + A4.y*col[17];
                        float u4 = A1.x*col[4]  + A2.w*col[11] + A4.z*col[18];
                        float u5 = A1.y*col[5]  + A3.x*col[12] + A4.w*col[19];
                        float u6 = A1.z*col[6]  + A3.y*col[13] + a20*col[20];
                        st = (((u0 + u1) + (u2 + u3)) + ((u4 + u5) + u6)) * ev;
                        if ((s & 7) == 7) {
                            unsigned eb = __float_as_uint(A0.x) >> 23;
                            eoff += (int)eb - 127;
                            st *= __uint_as_float((254u - eb) << 23);
                        }
                    } else {
                        float v0  = A0.x + col[0],  v1  = A0.y + col[1];
                        float v2  = A0.z + col[2],  v3  = A0.w + col[3];
                        float v4  = A1.x + col[4],  v5  = A1.y + col[5];
                        float v6  = A1.z + col[6],  v7  = A1.w + col[7];
                        float v8  = A2.x + col[8],  v9  = A2.y + col[9];
                        float v10 = A2.z + col[10], v11 = A2.w + col[11];
                        float v12 = A3.x + col[12], v13 = A3.y + col[13];
                        float v14 = A3.z + col[14], v15 = A3.w + col[15];
                        float v16 = A4.x + col[16], v17 = A4.y + col[17];
                        float v18 = A4.z + col[18], v19 = A4.w + col[19];
                        float v20 = a20 + col[20];
                        float m0 = fmaxf(v0, v1),   m1 = fmaxf(v2, v3);
                        float m2 = fmaxf(v4, v5),   m3 = fmaxf(v6, v7);
                        float m4 = fmaxf(v8, v9),   m5 = fmaxf(v10, v11);
                        float m6 = fmaxf(v12, v13), m7 = fmaxf(v14, v15);
                        float m8 = fmaxf(v16, v17), m9 = fmaxf(v18, v19);
                        float n0 = fmaxf(m0, m1), n1 = fmaxf(m2, m3);
                        float n2 = fmaxf(m4, m5), n3 = fmaxf(m6, m7);
                        float n4 = fmaxf(m8, m9);
                        st = fmaxf(fmaxf(fmaxf(n0, n1), fmaxf(n2, n3)),
                                   fmaxf(n4, v20)) + ev;
                    }
                }
                if (lane < NLAB) abuf[cb][s + 1][lane] = st;
            }
        }
        if (warp == 1) {
            if (it < 7) {
                const float* src = lg + (it + 1) * 64 * NLAB;
                float* dst = em[(it + 1) & 1];
                if (is_fwd) for (int k = lane; k < 64 * NLAB; k += 32) dst[k] = __expf(src[k]);
                else        for (int k = lane; k < 64 * NLAB; k += 32) dst[k] = src[k];
            }
            if (!is_fwd && it >= 1) {
                const int c = it - 1;
                const float4* src = (const float4*)&abuf[c & 1][1][0];
                float4* dst = (float4*)(g_alpha + ((size_t)b * TT + c * 64) * 24);
#pragma unroll
                for (int k = 0; k < 12; k++) dst[lane + 32 * k] = src[lane + 32 * k];
            }
        }
        __syncthreads();
    }

    if (is_fwd) {
        if (warp == 0) {
            float val = (lane < NLAB) ? st * __expf(endT[j]) : 0.0f;
#pragma unroll
            for (int w = 16; w; w >>= 1) val += __shfl_xor_sync(FULLMASK, val, w);
            if (lane == 0)
                atomicAdd(&out[LOSS_IDX],
                          (float)eoff * 0.69314718055994531f + __logf(val));
        }
    } else if (warp == 0) {
        float v = (lane < NLAB) ? (st + endT[j]) : NEG_BIG;
        float m = v;
#pragma unroll
        for (int w = 16; w; w >>= 1) m = fmaxf(m, __shfl_xor_sync(FULLMASK, m, w));
        unsigned bal = __ballot_sync(FULLMASK, v == m);
        if (lane == 0) g_lasttag[b] = __ffs(bal) - 1;
    }
}

// ---------------------------------------------------------------------------
// argmax_i(Arow[i] + Tt[x][i]) with lowest-index tie-break
// ---------------------------------------------------------------------------
__device__ __forceinline__ int chase_step(const float4* A, float a20,
                                          const float* tr)
{
    float4 B0 = *(const float4*)(tr);
    float4 B1 = *(const float4*)(tr + 4);
    float4 B2 = *(const float4*)(tr + 8);
    float4 B3 = *(const float4*)(tr + 12);
    float4 B4 = *(const float4*)(tr + 16);
    float  b20 = tr[20];
    float v[21];
    v[0]=A[0].x+B0.x; v[1]=A[0].y+B0.y; v[2]=A[0].z+B0.z; v[3]=A[0].w+B0.w;
    v[4]=A[1].x+B1.x; v[5]=A[1].y+B1.y; v[6]=A[1].z+B1.z; v[7]=A[1].w+B1.w;
    v[8]=A[2].x+B2.x; v[9]=A[2].y+B2.y; v[10]=A[2].z+B2.z; v[11]=A[2].w+B2.w;
    v[12]=A[3].x+B3.x; v[13]=A[3].y+B3.y; v[14]=A[3].z+B3.z; v[15]=A[3].w+B3.w;
    v[16]=A[4].x+B4.x; v[17]=A[4].y+B4.y; v[18]=A[4].z+B4.z; v[19]=A[4].w+B4.w;
    v[20]=a20+b20;
    float m0 = fmaxf(v[0], v[1]),   m1 = fmaxf(v[2], v[3]);
    float m2 = fmaxf(v[4], v[5]),   m3 = fmaxf(v[6], v[7]);
    float m4 = fmaxf(v[8], v[9]),   m5 = fmaxf(v[10], v[11]);
    float m6 = fmaxf(v[12], v[13]), m7 = fmaxf(v[14], v[15]);
    float m8 = fmaxf(v[16], v[17]), m9 = fmaxf(v[18], v[19]);
    float best = fmaxf(fmaxf(fmaxf(fmaxf(m0, m1), fmaxf(m2, m3)),
                             fmaxf(fmaxf(m4, m5), fmaxf(m6, m7))),
                       fmaxf(fmaxf(m8, m9), v[20]));
    int idx = 20;
#pragma unroll
    for (int i = 19; i >= 0; i--) idx = (v[i] == best) ? i : idx;
    return idx;
}

// ---------------------------------------------------------------------------
// k3 finalize: 64 blocks x 256. warp w = chunk w; lane = exit tag; chases run
// lane-parallel straight off g_alpha (no bp table). Then stitch + write tags.
// ---------------------------------------------------------------------------
__global__ __launch_bounds__(256)
void crf_fin(const float* __restrict__ trans, float* out)
{
    __shared__ float         Tt[NLAB][24];           // Tt[x][i] = trans[i][x]
    __shared__ unsigned char pathbuf[8][NLAB][64];
    __shared__ unsigned char entry_s[8][NLAB];
    __shared__ int           sel[8];

    const int b    = blockIdx.x;
    const int tid  = threadIdx.x;
    const int c    = tid >> 5;      // chunk
    const int lane = tid & 31;

    for (int k = tid; k < NLAB * NLAB; k += 256) {
        int i = k / NLAB, x = k - i * NLAB;
        Tt[x][i] = trans[k];
    }
    __syncthreads();

    if (lane < NLAB) {
        const int x0 = lane;
        const float* ab = g_alpha + (size_t)b * TT * 24;
        int cur = x0;
        pathbuf[c][x0][63] = (unsigned char)cur;

        // preload row t-1 for s=63
        const float* row = ab + (c * 64 + 62) * 24;
        float4 A[5];
        A[0] = *(const float4*)(row);      A[1] = *(const float4*)(row + 4);
        A[2] = *(const float4*)(row + 8);  A[3] = *(const float4*)(row + 12);
        A[4] = *(const float4*)(row + 16);
        float a20 = row[20];

#pragma unroll 1
        for (int s = 63; s >= 1; s--) {
            // prefetch next row (t-2) while argmax runs
            float4 N[5]; float n20 = 0.f;
            if (s > 1) {
                const float* nr = ab + (c * 64 + s - 2) * 24;
                N[0] = *(const float4*)(nr);      N[1] = *(const float4*)(nr + 4);
                N[2] = *(const float4*)(nr + 8);  N[3] = *(const float4*)(nr + 12);
                N[4] = *(const float4*)(nr + 16); n20 = nr[20];
            }
            cur = chase_step(A, a20, Tt[cur]);
            pathbuf[c][x0][s - 1] = (unsigned char)cur;
#pragma unroll
            for (int q = 0; q < 5; q++) A[q] = N[q];
            a20 = n20;
        }
        if (c > 0) {
            const float* er = ab + (c * 64 - 1) * 24;
            float4 E[5];
            E[0] = *(const float4*)(er);      E[1] = *(const float4*)(er + 4);
            E[2] = *(const float4*)(er + 8);  E[3] = *(const float4*)(er + 12);
            E[4] = *(const float4*)(er + 16);
            entry_s[c][x0] = (unsigned char)chase_step(E, er[20], Tt[cur]);
        }
    }
    __syncthreads();

    if (tid == 0) {
        int x = g_lasttag[b];
#pragma unroll
        for (int cc = 7; cc >= 0; cc--) {
            sel[cc] = x;
            x = (cc > 0) ? entry_s[cc][x] : 0;
        }
    }
    __syncthreads();

    for (int t = tid; t < TT; t += 256) {
        int cc = t >> 6;
        out[TAGS_BASE + (size_t)b * TT + t] = (float)pathbuf[cc][sel[cc]][t & 63];
    }
}

extern "C" void kernel_launch(void* const* d_in, const int* in_sizes, int n_in,
                              void* d_out, int out_size)
{
    const float* mlm    = (const float*)d_in[0];
    const int*   gold   = (const int*)  d_in[2];
    const float* W      = (const float*)d_in[3];
    const float* bias   = (const float*)d_in[4];
    const float* trans  = (const float*)d_in[5];
    const float* startT = (const float*)d_in[6];
    const float* endT   = (const float*)d_in[7];
    float* out = (float*)d_out;

    gemm_kernel<<<128, 128>>>(mlm, W, bias, out);
    crf_chain<<<160, 64>>>(out, gold, trans, startT, endT, out);
    crf_fin<<<BB, 256>>>(trans, out);
}